// round 3
// baseline (speedup 1.0000x reference)
#include <cuda_runtime.h>
#include <cuda_bf16.h>
#include <math.h>

// Problem constants
#define S_TOK   704          // tokens per view (16*44)
#define DMODEL  512
#define NHEADS  8
#define HDIM    64
#define NVIEW   6
#define TKV     3520         // 5 * 704
#define LMK     16
#define IMG_H   256
#define IMG_W   704
#define SPLITK  16           // split-K for the pe patch-embed GEMM

// ---------------- scratch (static device arrays; no allocation allowed) ----
__device__ float g_maskf[S_TOK];
__device__ float g_tokens[NVIEW * S_TOK * DMODEL];          // 8.7 MB
__device__ float g_qkv[NVIEW * S_TOK * 3 * DMODEL];         // 26 MB
__device__ float g_fpart[SPLITK * S_TOK * DMODEL];          // 23 MB (split-K partials)
__device__ float g_fpe[S_TOK * DMODEL];
__device__ float g_qn[NHEADS * S_TOK * HDIM];
__device__ float g_kn[NHEADS * TKV * HDIM];                 // 7.2 MB
__device__ float g_vv[NHEADS * TKV * HDIM];                 // 7.2 MB
__device__ float g_qL[NHEADS * LMK * HDIM];
__device__ float g_kL[NHEADS * LMK * HDIM];
__device__ float g_a1[NHEADS * S_TOK * LMK];
__device__ float g_tmp[NHEADS * LMK * HDIM];
__device__ float g_vals[S_TOK * DMODEL];

// ---------------- mask (16x16 avg-pool > 0) ------------------------------
__global__ void maskf_kernel(const float* __restrict__ mm) {
    int p = blockIdx.x * blockDim.x + threadIdx.x;
    if (p >= S_TOK) return;
    int gh = p / 44, gw = p % 44;
    float s = 0.f;
    for (int i = 0; i < 16; i++) {
        const float* r = mm + (size_t)(gh * 16 + i) * IMG_W + gw * 16;
        for (int j = 0; j < 16; j++) s += r[j];
    }
    g_maskf[p] = ((s * (1.f / 256.f)) > 0.f) ? 1.f : 0.f;
}

// ============================================================================
// bf16-split tensor-core GEMM core.
// Block tile 64(M) x 64(N), BK=16, 128 threads = 4 warps in 2x2 (warp tile
// 32x32 = 2 m16-frags x 4 n8-frags of mma.m16n8k16.bf16).
// Emulated fp32 via 2-term bf16 split: x = hi + lo; C += Ahi*Bhi + Ahi*Blo
// + Alo*Bhi (lo*lo dropped, ~2^-18 per term). Loader converts fp32 -> packed
// bf16x2 pairs (k-major, stride 72 words => conflict-free LDS/STS).
// ============================================================================

__device__ __forceinline__ void split2(float x, float y,
                                       unsigned& hi, unsigned& lo) {
    __nv_bfloat16 hx = __float2bfloat16_rn(x);
    __nv_bfloat16 hy = __float2bfloat16_rn(y);
    float lx = x - __bfloat162float(hx);
    float ly = y - __bfloat162float(hy);
    __nv_bfloat162 hp = __halves2bfloat162(hx, hy);      // low 16 bits = x
    __nv_bfloat162 lp = __floats2bfloat162_rn(lx, ly);
    hi = *reinterpret_cast<unsigned*>(&hp);
    lo = *reinterpret_cast<unsigned*>(&lp);
}

__device__ __forceinline__ void mma_bf16(float* c, const unsigned* a,
                                         const unsigned* b) {
    asm("mma.sync.aligned.m16n8k16.row.col.f32.bf16.bf16.f32 "
        "{%0,%1,%2,%3}, {%4,%5,%6,%7}, {%8,%9}, {%0,%1,%2,%3};"
        : "+f"(c[0]), "+f"(c[1]), "+f"(c[2]), "+f"(c[3])
        : "r"(a[0]), "r"(a[1]), "r"(a[2]), "r"(a[3]),
          "r"(b[0]), "r"(b[1]));
}

#define DECL_TILE_BF()                                                         \
    __shared__ unsigned sAh[2][8][72], sAl[2][8][72];                          \
    __shared__ unsigned sBh[2][8][72], sBl[2][8][72];                          \
    int tid = threadIdx.x;                                                     \
    int lrow = tid & 63;                                                       \
    int lk8 = (tid >> 6) << 3;                                                 \
    int kp0 = lk8 >> 1;                                                        \
    int warp = tid >> 5, lane = tid & 31;                                      \
    int g = lane >> 2, tig = lane & 3;                                         \
    int wm = (warp >> 1) << 5, wn = (warp & 1) << 5;                           \
    float acc[2][4][4] = {};                                                   \
    float4 av0, av1, bv0, bv1;

#define STORE_SMEM_BF(B_) do {                                                 \
    unsigned h_, l_;                                                           \
    split2(av0.x, av0.y, h_, l_);                                              \
    sAh[B_][kp0 + 0][lrow] = h_; sAl[B_][kp0 + 0][lrow] = l_;                  \
    split2(av0.z, av0.w, h_, l_);                                              \
    sAh[B_][kp0 + 1][lrow] = h_; sAl[B_][kp0 + 1][lrow] = l_;                  \
    split2(av1.x, av1.y, h_, l_);                                              \
    sAh[B_][kp0 + 2][lrow] = h_; sAl[B_][kp0 + 2][lrow] = l_;                  \
    split2(av1.z, av1.w, h_, l_);                                              \
    sAh[B_][kp0 + 3][lrow] = h_; sAl[B_][kp0 + 3][lrow] = l_;                  \
    split2(bv0.x, bv0.y, h_, l_);                                              \
    sBh[B_][kp0 + 0][lrow] = h_; sBl[B_][kp0 + 0][lrow] = l_;                  \
    split2(bv0.z, bv0.w, h_, l_);                                              \
    sBh[B_][kp0 + 1][lrow] = h_; sBl[B_][kp0 + 1][lrow] = l_;                  \
    split2(bv1.x, bv1.y, h_, l_);                                              \
    sBh[B_][kp0 + 2][lrow] = h_; sBl[B_][kp0 + 2][lrow] = l_;                  \
    split2(bv1.z, bv1.w, h_, l_);                                              \
    sBh[B_][kp0 + 3][lrow] = h_; sBl[B_][kp0 + 3][lrow] = l_;                  \
} while (0)

// mma.m16n8k16 fragment fetch. A (row-major 16x16): regs (pairs along k):
//   a0=(g,   kp=tig)  a1=(g+8, kp=tig)  a2=(g,   kp=tig+4)  a3=(g+8, kp=tig+4)
// B (col 16x8): b0=(kp=tig, n=g)  b1=(kp=tig+4, n=g)
#define COMPUTE_BF(B_) do {                                                    \
    unsigned Ah_[2][4], Al_[2][4], Bh_[4][2], Bl_[4][2];                       \
    _Pragma("unroll")                                                          \
    for (int fm_ = 0; fm_ < 2; fm_++) {                                        \
        int mb_ = wm + fm_ * 16;                                               \
        Ah_[fm_][0] = sAh[B_][tig][mb_ + g];                                   \
        Ah_[fm_][1] = sAh[B_][tig][mb_ + g + 8];                               \
        Ah_[fm_][2] = sAh[B_][tig + 4][mb_ + g];                               \
        Ah_[fm_][3] = sAh[B_][tig + 4][mb_ + g + 8];                           \
        Al_[fm_][0] = sAl[B_][tig][mb_ + g];                                   \
        Al_[fm_][1] = sAl[B_][tig][mb_ + g + 8];                               \
        Al_[fm_][2] = sAl[B_][tig + 4][mb_ + g];                               \
        Al_[fm_][3] = sAl[B_][tig + 4][mb_ + g + 8];                           \
    }                                                                          \
    _Pragma("unroll")                                                          \
    for (int fn_ = 0; fn_ < 4; fn_++) {                                        \
        int nb_ = wn + fn_ * 8;                                                \
        Bh_[fn_][0] = sBh[B_][tig][nb_ + g];                                   \
        Bh_[fn_][1] = sBh[B_][tig + 4][nb_ + g];                               \
        Bl_[fn_][0] = sBl[B_][tig][nb_ + g];                                   \
        Bl_[fn_][1] = sBl[B_][tig + 4][nb_ + g];                               \
    }                                                                          \
    _Pragma("unroll")                                                          \
    for (int fm_ = 0; fm_ < 2; fm_++)                                          \
        _Pragma("unroll")                                                      \
        for (int fn_ = 0; fn_ < 4; fn_++) {                                    \
            mma_bf16(acc[fm_][fn_], Ah_[fm_], Bh_[fn_]);                       \
            mma_bf16(acc[fm_][fn_], Ah_[fm_], Bl_[fn_]);                       \
            mma_bf16(acc[fm_][fn_], Al_[fm_], Bh_[fn_]);                       \
        }                                                                      \
} while (0)

// ---------------- generic NT GEMM (bf16-split): C = A*B^T + bias -----------
// M%64==0, N%64==0, K%16==0.
__global__ __launch_bounds__(128) void gemm_nt_bf16_kernel(
    const float* __restrict__ A, int lda,
    const float* __restrict__ B, int ldb,
    const float* __restrict__ bias,
    float* __restrict__ C, int ldc, int K)
{
    DECL_TILE_BF();
    const float* Ab = A + (size_t)(blockIdx.x * 64 + lrow) * lda + lk8;
    const float* Bb = B + (size_t)(blockIdx.y * 64 + lrow) * ldb + lk8;
    int NT = K >> 4;
    av0 = *(const float4*)(Ab);     av1 = *(const float4*)(Ab + 4);
    bv0 = *(const float4*)(Bb);     bv1 = *(const float4*)(Bb + 4);
    STORE_SMEM_BF(0);
    __syncthreads();
    int buf = 0;
    for (int t = 1; t < NT; t++) {
        const float* Ak = Ab + t * 16;
        const float* Bk = Bb + t * 16;
        av0 = *(const float4*)(Ak); av1 = *(const float4*)(Ak + 4);
        bv0 = *(const float4*)(Bk); bv1 = *(const float4*)(Bk + 4);
        COMPUTE_BF(buf);
        STORE_SMEM_BF(buf ^ 1);
        __syncthreads();
        buf ^= 1;
    }
    COMPUTE_BF(buf);
    int m0 = blockIdx.x * 64 + wm;
    int n0 = blockIdx.y * 64 + wn;
#pragma unroll
    for (int fm = 0; fm < 2; fm++)
#pragma unroll
        for (int fn = 0; fn < 4; fn++) {
            int r = m0 + fm * 16 + g;
            int c = n0 + fn * 8 + 2 * tig;
            float2 bb = *(const float2*)(bias + c);
            float2 v0, v1;
            v0.x = acc[fm][fn][0] + bb.x; v0.y = acc[fm][fn][1] + bb.y;
            v1.x = acc[fm][fn][2] + bb.x; v1.y = acc[fm][fn][3] + bb.y;
            *(float2*)(C + (size_t)r * ldc + c) = v0;
            *(float2*)(C + (size_t)(r + 8) * ldc + c) = v1;
        }
}

// ---------------- patch-embed GEMM for pe (K=65536), bf16-split, split-K ---
// Each z handles 256 k-tiles of 16 -> partials in g_fpart[z] (no bias).
__global__ __launch_bounds__(128) void gemm_pe_bf16_kernel(
    const float* __restrict__ pe, const float* __restrict__ W,
    const int* __restrict__ ftp)
{
    DECL_TILE_BF();
    int z = blockIdx.z;
    const float* img = pe + (size_t)(*ftp) * 256 * IMG_H * IMG_W;
    int s = blockIdx.x * 64 + lrow;
    int gh = s / 44, gw = s % 44;
    const float* Arow = img + gw * 16 + lk8;
    const float* Bb = W + (size_t)(blockIdx.y * 64 + lrow) * 65536 + lk8;
    int kt0 = z * 256;

#define LOAD_PE(kt_) do {                                                      \
    int c_ = (kt_) >> 4, rr_ = (kt_) & 15;                                     \
    const float* ap_ = Arow + (size_t)(c_ * IMG_H + gh * 16 + rr_) * IMG_W;    \
    av0 = *(const float4*)(ap_); av1 = *(const float4*)(ap_ + 4);              \
    const float* bp_ = Bb + (size_t)(kt_) * 16;                                \
    bv0 = *(const float4*)(bp_); bv1 = *(const float4*)(bp_ + 4);              \
} while (0)

    LOAD_PE(kt0);
    STORE_SMEM_BF(0);
    __syncthreads();
    int buf = 0;
    for (int t = 1; t < 256; t++) {
        LOAD_PE(kt0 + t);
        COMPUTE_BF(buf);
        STORE_SMEM_BF(buf ^ 1);
        __syncthreads();
        buf ^= 1;
    }
    COMPUTE_BF(buf);
    int m0 = blockIdx.x * 64 + wm;
    int n0 = blockIdx.y * 64 + wn;
    float* out = g_fpart + (size_t)z * S_TOK * DMODEL;
#pragma unroll
    for (int fm = 0; fm < 2; fm++)
#pragma unroll
        for (int fn = 0; fn < 4; fn++) {
            int r = m0 + fm * 16 + g;
            int c = n0 + fn * 8 + 2 * tig;
            float2 v0, v1;
            v0.x = acc[fm][fn][0]; v0.y = acc[fm][fn][1];
            v1.x = acc[fm][fn][2]; v1.y = acc[fm][fn][3];
            *(float2*)(out + (size_t)r * DMODEL + c) = v0;
            *(float2*)(out + (size_t)(r + 8) * DMODEL + c) = v1;
        }
}

// ============================================================================
// fp32 SIMT GEMM (kept for the small tokens patch-embed, K=768, mask epilogue)
// 64x64 tile, BK=16, 128 threads, 8x4 microtile, double-buffered.
// ============================================================================
#define DECL_TILE()                                                            \
    __shared__ float As[2][16][64];                                            \
    __shared__ float Bs[2][16][64];                                            \
    int tid = threadIdx.x;                                                     \
    int lrow = tid & 63;                                                       \
    int lk8 = (tid >> 6) << 3;                                                 \
    int tx4 = (tid & 15) << 2;                                                 \
    int ty8 = (tid >> 4) << 3;                                                 \
    float acc[8][4] = {};                                                      \
    float4 av0, av1, bv0, bv1;

#define STORE_SMEM(B_) do {                                                    \
    As[B_][lk8 + 0][lrow] = av0.x; As[B_][lk8 + 1][lrow] = av0.y;              \
    As[B_][lk8 + 2][lrow] = av0.z; As[B_][lk8 + 3][lrow] = av0.w;              \
    As[B_][lk8 + 4][lrow] = av1.x; As[B_][lk8 + 5][lrow] = av1.y;              \
    As[B_][lk8 + 6][lrow] = av1.z; As[B_][lk8 + 7][lrow] = av1.w;              \
    Bs[B_][lk8 + 0][lrow] = bv0.x; Bs[B_][lk8 + 1][lrow] = bv0.y;              \
    Bs[B_][lk8 + 2][lrow] = bv0.z; Bs[B_][lk8 + 3][lrow] = bv0.w;              \
    Bs[B_][lk8 + 4][lrow] = bv1.x; Bs[B_][lk8 + 5][lrow] = bv1.y;              \
    Bs[B_][lk8 + 6][lrow] = bv1.z; Bs[B_][lk8 + 7][lrow] = bv1.w;              \
} while (0)

#define COMPUTE_SMEM(B_) do {                                                  \
    _Pragma("unroll")                                                          \
    for (int k_ = 0; k_ < 16; k_++) {                                          \
        float4 a0 = *(const float4*)&As[B_][k_][ty8];                          \
        float4 a1 = *(const float4*)&As[B_][k_][ty8 + 4];                      \
        float4 b  = *(const float4*)&Bs[B_][k_][tx4];                          \
        float a_[8] = {a0.x, a0.y, a0.z, a0.w, a1.x, a1.y, a1.z, a1.w};        \
        _Pragma("unroll")                                                      \
        for (int i_ = 0; i_ < 8; i_++) {                                       \
            acc[i_][0] += a_[i_] * b.x; acc[i_][1] += a_[i_] * b.y;            \
            acc[i_][2] += a_[i_] * b.z; acc[i_][3] += a_[i_] * b.w;            \
        }                                                                      \
    }                                                                          \
} while (0)

// ---------------- patch-embed GEMM for x (6 views, C_in=3, K=768) ----------
__global__ __launch_bounds__(128) void gemm_tokens_kernel(
    const float* __restrict__ x, const float* __restrict__ W,
    const float* __restrict__ bias)
{
    DECL_TILE();
    int v = blockIdx.z;
    const float* img = x + (size_t)v * 3 * IMG_H * IMG_W;
    int s = blockIdx.x * 64 + lrow;
    int gh = s / 44, gw = s % 44;
    const float* Arow = img + gw * 16 + lk8;
    const float* Bb = W + (size_t)(blockIdx.y * 64 + lrow) * 768 + lk8;

#define LOAD_TOK(kt_) do {                                                     \
    int c_ = (kt_) >> 4, rr_ = (kt_) & 15;                                     \
    const float* ap_ = Arow + (size_t)(c_ * IMG_H + gh * 16 + rr_) * IMG_W;    \
    av0 = *(const float4*)(ap_); av1 = *(const float4*)(ap_ + 4);              \
    const float* bp_ = Bb + (kt_) * 16;                                        \
    bv0 = *(const float4*)(bp_); bv1 = *(const float4*)(bp_ + 4);              \
} while (0)

    LOAD_TOK(0);
    STORE_SMEM(0);
    __syncthreads();
    int buf = 0;
    for (int t = 1; t < 48; t++) {
        LOAD_TOK(t);
        COMPUTE_SMEM(buf);
        STORE_SMEM(buf ^ 1);
        __syncthreads();
        buf ^= 1;
    }
    COMPUTE_SMEM(buf);
    int m = blockIdx.x * 64 + ty8;
    int n = blockIdx.y * 64 + tx4;
    float4 bb = *(const float4*)(bias + n);
    float* out = g_tokens + (size_t)v * S_TOK * DMODEL;
#pragma unroll
    for (int i = 0; i < 8; i++) {
        float mk = g_maskf[m + i];
        float4 r;
        r.x = (acc[i][0] + bb.x) * mk; r.y = (acc[i][1] + bb.y) * mk;
        r.z = (acc[i][2] + bb.z) * mk; r.w = (acc[i][3] + bb.w) * mk;
        *(float4*)(out + (size_t)(m + i) * DMODEL + n) = r;
    }
}

// Reduce split-K partials, add bias, apply mask -> g_fpe
__global__ void fpe_reduce_kernel(const float* __restrict__ peb) {
    int idx = blockIdx.x * blockDim.x + threadIdx.x;
    if (idx >= S_TOK * DMODEL) return;
    int s = idx >> 9, d = idx & 511;
    float a = 0.f;
#pragma unroll
    for (int z = 0; z < SPLITK; z++)
        a += g_fpart[(size_t)z * S_TOK * DMODEL + idx];
    g_fpe[idx] = (a + peb[d]) * g_maskf[s];
}

// ---------------- q = qkv[ft].q + fpe, then l2-normalize -> g_qn -----------
__global__ void qn_kernel(const int* __restrict__ ftp) {
    int gw = (blockIdx.x * blockDim.x + threadIdx.x) >> 5;
    int lane = threadIdx.x & 31;
    if (gw >= NHEADS * S_TOK) return;
    int h = gw / S_TOK, s = gw % S_TOK;
    int ft = *ftp;
    const float* q = g_qkv + ((size_t)ft * S_TOK + s) * 1536 + h * 192;
    const float* f = g_fpe + (size_t)s * DMODEL + h * 64;
    float v1 = q[lane] + f[lane];
    float v2 = q[lane + 32] + f[lane + 32];
    float ss = v1 * v1 + v2 * v2;
#pragma unroll
    for (int o = 16; o; o >>= 1) ss += __shfl_xor_sync(0xffffffffu, ss, o);
    float inv = 1.f / fmaxf(sqrtf(ss), 1e-12f);
    float* o_ = g_qn + ((size_t)h * S_TOK + s) * HDIM;
    o_[lane] = v1 * inv;
    o_[lane + 32] = v2 * inv;
}

// ---------------- k (normalized) and v (raw) for the 5 other views ---------
__global__ void kvn_kernel(const int* __restrict__ ftp) {
    int gw = (blockIdx.x * blockDim.x + threadIdx.x) >> 5;
    int lane = threadIdx.x & 31;
    if (gw >= NHEADS * TKV) return;
    int h = gw / TKV, t = gw % TKV;
    int vi = t / S_TOK, s = t % S_TOK;
    int ft = *ftp;
    int ov = vi + (vi >= ft ? 1 : 0);
    const float* base = g_qkv + ((size_t)ov * S_TOK + s) * 1536 + h * 192;
    float k1 = base[64 + lane];
    float k2 = base[96 + lane];
    float ss = k1 * k1 + k2 * k2;
#pragma unroll
    for (int o = 16; o; o >>= 1) ss += __shfl_xor_sync(0xffffffffu, ss, o);
    float inv = 1.f / fmaxf(sqrtf(ss), 1e-12f);
    float* ko = g_kn + ((size_t)h * TKV + t) * HDIM;
    ko[lane] = k1 * inv;
    ko[lane + 32] = k2 * inv;
    float* vo = g_vv + ((size_t)h * TKV + t) * HDIM;
    vo[lane] = base[128 + lane];
    vo[lane + 32] = base[160 + lane];
}

// ---------------- landmarks (uniform bin means) ----------------------------
__global__ void qland_kernel() {
    int idx = blockIdx.x * blockDim.x + threadIdx.x;
    if (idx >= NHEADS * LMK * HDIM) return;
    int e = idx & 63, l = (idx >> 6) & 15, h = idx >> 10;
    const float* base = g_qn + ((size_t)h * S_TOK + l * 44) * HDIM + e;
    float a = 0.f;
    for (int i = 0; i < 44; i++) a += base[(size_t)i * HDIM];
    g_qL[idx] = a * (1.f / 44.f);
}
__global__ void kland_kernel() {
    int idx = blockIdx.x * blockDim.x + threadIdx.x;
    if (idx >= NHEADS * LMK * HDIM) return;
    int e = idx & 63, l = (idx >> 6) & 15, h = idx >> 10;
    const float* base = g_kn + ((size_t)h * TKV + l * 220) * HDIM + e;
    float a = 0.f;
    for (int i = 0; i < 220; i++) a += base[(size_t)i * HDIM];
    g_kL[idx] = a * (1.f / 220.f);
}

// ---------------- a1 = softmax_l(qn . kL * scale) --------------------------
__global__ void a1_kernel() {
    int b = blockIdx.x;               // h*704 + s
    int lane = threadIdx.x;
    int h = b / S_TOK, s = b % S_TOK;
    const float* q = g_qn + ((size_t)h * S_TOK + s) * HDIM;
    float q1 = q[lane], q2 = q[lane + 32];
    const float* kl = g_kL + (size_t)h * LMK * HDIM;
    float dot[LMK];
#pragma unroll
    for (int l = 0; l < LMK; l++) {
        float p = q1 * kl[l * HDIM + lane] + q2 * kl[l * HDIM + lane + 32];
#pragma unroll
        for (int o = 16; o; o >>= 1) p += __shfl_xor_sync(0xffffffffu, p, o);
        dot[l] = p * 0.125f;
    }
    float m = dot[0];
#pragma unroll
    for (int l = 1; l < LMK; l++) m = fmaxf(m, dot[l]);
    float sm = 0.f;
#pragma unroll
    for (int l = 0; l < LMK; l++) { dot[l] = expf(dot[l] - m); sm += dot[l]; }
    float inv = 1.f / sm;
    if (lane < LMK)
        g_a1[((size_t)h * S_TOK + s) * LMK + lane] = dot[lane] * inv;
}

// ---------------- a2 = softmax_t(qL . kn * scale); tmp = a2 @ v ------------
__global__ __launch_bounds__(256) void a2_kernel() {
    __shared__ float sq[HDIM];
    __shared__ float red[256];
    __shared__ float p[TKV];
    int hb = blockIdx.x;
    int h = hb >> 4, l = hb & 15;
    int tid = threadIdx.x;
    if (tid < HDIM) sq[tid] = g_qL[((size_t)h * LMK + l) * HDIM + tid];
    __syncthreads();
    const float4* sq4 = (const float4*)sq;
    float lmax = -1e30f;
    for (int t = tid; t < TKV; t += 256) {
        const float4* kr = (const float4*)(g_kn + ((size_t)h * TKV + t) * HDIM);
        float d = 0.f;
#pragma unroll
        for (int i = 0; i < 16; i++) {
            float4 a = sq4[i], b = kr[i];
            d += a.x * b.x + a.y * b.y + a.z * b.z + a.w * b.w;
        }
        d *= 0.125f;
        p[t] = d;
        lmax = fmaxf(lmax, d);
    }
    red[tid] = lmax;
    __syncthreads();
    for (int o = 128; o; o >>= 1) {
        if (tid < o) red[tid] = fmaxf(red[tid], red[tid + o]);
        __syncthreads();
    }
    float M = red[0];
    __syncthreads();
    float lsum = 0.f;
    for (int t = tid; t < TKV; t += 256) {
        float e = expf(p[t] - M);
        p[t] = e;
        lsum += e;
    }
    red[tid] = lsum;
    __syncthreads();
    for (int o = 128; o; o >>= 1) {
        if (tid < o) red[tid] += red[tid + o];
        __syncthreads();
    }
    float inv = 1.f / red[0];
    __syncthreads();
    int e = tid & 63, gq = tid >> 6;
    float acc2 = 0.f;
    for (int t = gq; t < TKV; t += 4)
        acc2 += p[t] * g_vv[((size_t)h * TKV + t) * HDIM + e];
    red[tid] = acc2;
    __syncthreads();
    if (tid < HDIM)
        g_tmp[((size_t)h * LMK + l) * HDIM + tid] =
            (red[tid] + red[tid + 64] + red[tid + 128] + red[tid + 192]) * inv;
}

// ---------------- vals = a1 @ tmp, laid out (s, h*64+e) --------------------
__global__ void vals_kernel() {
    int idx = blockIdx.x * blockDim.x + threadIdx.x;
    if (idx >= S_TOK * DMODEL) return;
    int s = idx >> 9, d = idx & 511;
    int h = d >> 6, e = d & 63;
    const float* a = g_a1 + ((size_t)h * S_TOK + s) * LMK;
    const float* t = g_tmp + (size_t)h * LMK * HDIM + e;
    float acc2 = 0.f;
#pragma unroll
    for (int l = 0; l < LMK; l++) acc2 += a[l] * t[(size_t)l * HDIM];
    g_vals[idx] = acc2;
}

// ---------------- launch ---------------------------------------------------
extern "C" void kernel_launch(void* const* d_in, const int* in_sizes, int n_in,
                              void* d_out, int out_size)
{
    const float* x   = (const float*)d_in[0];
    const float* pe  = (const float*)d_in[1];
    const float* mm  = (const float*)d_in[2];
    const float* ciw = (const float*)d_in[3];
    const float* cib = (const float*)d_in[4];
    const float* cpw = (const float*)d_in[5];
    const float* cpb = (const float*)d_in[6];
    const float* qw  = (const float*)d_in[7];
    const float* qb  = (const float*)d_in[8];
    const float* ow  = (const float*)d_in[9];
    const float* ob  = (const float*)d_in[10];
    const int*   ftp = (const int*)d_in[11];
    float* out = (float*)d_out;

    float *p_tokens, *p_qkv, *p_vals;
    cudaGetSymbolAddress((void**)&p_tokens, g_tokens);
    cudaGetSymbolAddress((void**)&p_qkv, g_qkv);
    cudaGetSymbolAddress((void**)&p_vals, g_vals);

    maskf_kernel<<<3, 256>>>(mm);

    dim3 gt(11, 8, 6);
    gemm_tokens_kernel<<<gt, 128>>>(x, ciw, cib);

    dim3 gp(11, 8, SPLITK);
    gemm_pe_bf16_kernel<<<gp, 128>>>(pe, cpw, ftp);
    fpe_reduce_kernel<<<(S_TOK * DMODEL + 255) / 256, 256>>>(cpb);

    // qkv for all 6 views: (4224 x 512) @ (1536 x 512)^T
    gemm_nt_bf16_kernel<<<dim3(66, 24), 128>>>(p_tokens, 512, qw, 512, qb,
                                               p_qkv, 1536, 512);

    qn_kernel<<<(NHEADS * S_TOK * 32 + 255) / 256, 256>>>(ftp);
    kvn_kernel<<<(NHEADS * TKV * 32 + 255) / 256, 256>>>(ftp);
    qland_kernel<<<(NHEADS * LMK * HDIM + 255) / 256, 256>>>();
    kland_kernel<<<(NHEADS * LMK * HDIM + 255) / 256, 256>>>();
    a1_kernel<<<NHEADS * S_TOK, 32>>>();
    a2_kernel<<<NHEADS * LMK, 256>>>();
    vals_kernel<<<(S_TOK * DMODEL + 255) / 256, 256>>>();

    // out = vals(704x512) @ o_w(512x512)^T + o_b
    gemm_nt_bf16_kernel<<<dim3(11, 8), 128>>>(p_vals, 512, ow, 512, ob,
                                              out, 512, 512);
}

// round 5
// speedup vs baseline: 1.3236x; 1.3236x over previous
#include <cuda_runtime.h>
#include <cuda_bf16.h>
#include <math.h>

// Problem constants
#define S_TOK   704          // tokens per view (16*44)
#define DMODEL  512
#define NHEADS  8
#define HDIM    64
#define NVIEW   6
#define TKV     3520         // 5 * 704
#define LMK     16
#define IMG_H   256
#define IMG_W   704
#define SPLITK  32           // split-K for the pe patch-embed GEMM

// ---------------- scratch (static device arrays; no allocation allowed) ----
__device__ float g_maskf[S_TOK];
__device__ float g_tokens[NVIEW * S_TOK * DMODEL];          // 8.7 MB
__device__ float g_qkv[NVIEW * S_TOK * 3 * DMODEL];         // 26 MB
__device__ float g_fpart[SPLITK * S_TOK * DMODEL];          // 46 MB (split-K partials)
__device__ float g_fpe[S_TOK * DMODEL];
__device__ float g_qn[NHEADS * S_TOK * HDIM];
__device__ float g_kn[NHEADS * TKV * HDIM];                 // 7.2 MB
__device__ float g_vv[NHEADS * TKV * HDIM];                 // 7.2 MB
__device__ float g_qL[NHEADS * LMK * HDIM];
__device__ float g_kL[NHEADS * LMK * HDIM];
__device__ float g_a1[NHEADS * S_TOK * LMK];
__device__ float g_tmp[NHEADS * LMK * HDIM];
__device__ float g_vals[768 * DMODEL];                      // padded to 768 rows (zero-init)

// ---------------- mask (16x16 avg-pool > 0) ------------------------------
__global__ void maskf_kernel(const float* __restrict__ mm) {
    int p = blockIdx.x * blockDim.x + threadIdx.x;
    if (p >= S_TOK) return;
    int gh = p / 44, gw = p % 44;
    float s = 0.f;
    for (int i = 0; i < 16; i++) {
        const float* r = mm + (size_t)(gh * 16 + i) * IMG_W + gw * 16;
        for (int j = 0; j < 16; j++) s += r[j];
    }
    g_maskf[p] = ((s * (1.f / 256.f)) > 0.f) ? 1.f : 0.f;
}

// ============================================================================
// bf16-split tensor-core GEMM core, 128x128 block tile, BK=16, 256 threads.
// 8 warps in 2(M) x 4(N); warp tile 64x32 = 4 m16-frags x 4 n8-frags of
// mma.m16n8k16.bf16. fp32 emulated via 2-term bf16 split:
//   C += Ahi*Bhi + Ahi*Blo + Alo*Bhi   (lo*lo dropped, ~2^-18/term)
// Loader: 256 threads each handle one (row 0..127, k-half) of A and of B,
// converting fp32 -> packed bf16x2 k-pairs. smem row stride 136 words
// (136 mod 32 == 8 -> compute banks tig*8+g all-distinct; loader rows
// consecutive) => all STS/LDS conflict-free.
// Fragment mapping is byte-identical to the round-3 kernel that PASSED with
// rel_err 7.0e-6.
// ============================================================================

__device__ __forceinline__ void split2(float x, float y,
                                       unsigned& hi, unsigned& lo) {
    __nv_bfloat16 hx = __float2bfloat16_rn(x);
    __nv_bfloat16 hy = __float2bfloat16_rn(y);
    float lx = x - __bfloat162float(hx);
    float ly = y - __bfloat162float(hy);
    __nv_bfloat162 hp = __halves2bfloat162(hx, hy);      // low 16 bits = x
    __nv_bfloat162 lp = __floats2bfloat162_rn(lx, ly);
    hi = *reinterpret_cast<unsigned*>(&hp);
    lo = *reinterpret_cast<unsigned*>(&lp);
}

__device__ __forceinline__ void mma_bf16(float* c, const unsigned* a,
                                         const unsigned* b) {
    asm("mma.sync.aligned.m16n8k16.row.col.f32.bf16.bf16.f32 "
        "{%0,%1,%2,%3}, {%4,%5,%6,%7}, {%8,%9}, {%0,%1,%2,%3};"
        : "+f"(c[0]), "+f"(c[1]), "+f"(c[2]), "+f"(c[3])
        : "r"(a[0]), "r"(a[1]), "r"(a[2]), "r"(a[3]),
          "r"(b[0]), "r"(b[1]));
}

#define DECL_TILE_BF()                                                         \
    __shared__ unsigned sAh[2][8][136], sAl[2][8][136];                        \
    __shared__ unsigned sBh[2][8][136], sBl[2][8][136];                        \
    int tid = threadIdx.x;                                                     \
    int lrow = tid & 127;                                                      \
    int lk8 = (tid >> 7) << 3;                                                 \
    int kp0 = lk8 >> 1;                                                        \
    int warp = tid >> 5, lane = tid & 31;                                      \
    int g = lane >> 2, tig = lane & 3;                                         \
    int wm = (warp >> 2) << 6, wn = (warp & 3) << 5;                           \
    float acc[4][4][4] = {};                                                   \
    float4 av0, av1, bv0, bv1;

#define STORE_SMEM_BF(B_) do {                                                 \
    unsigned h_, l_;                                                           \
    split2(av0.x, av0.y, h_, l_);                                              \
    sAh[B_][kp0 + 0][lrow] = h_; sAl[B_][kp0 + 0][lrow] = l_;                  \
    split2(av0.z, av0.w, h_, l_);                                              \
    sAh[B_][kp0 + 1][lrow] = h_; sAl[B_][kp0 + 1][lrow] = l_;                  \
    split2(av1.x, av1.y, h_, l_);                                              \
    sAh[B_][kp0 + 2][lrow] = h_; sAl[B_][kp0 + 2][lrow] = l_;                  \
    split2(av1.z, av1.w, h_, l_);                                              \
    sAh[B_][kp0 + 3][lrow] = h_; sAl[B_][kp0 + 3][lrow] = l_;                  \
    split2(bv0.x, bv0.y, h_, l_);                                              \
    sBh[B_][kp0 + 0][lrow] = h_; sBl[B_][kp0 + 0][lrow] = l_;                  \
    split2(bv0.z, bv0.w, h_, l_);                                              \
    sBh[B_][kp0 + 1][lrow] = h_; sBl[B_][kp0 + 1][lrow] = l_;                  \
    split2(bv1.x, bv1.y, h_, l_);                                              \
    sBh[B_][kp0 + 2][lrow] = h_; sBl[B_][kp0 + 2][lrow] = l_;                  \
    split2(bv1.z, bv1.w, h_, l_);                                              \
    sBh[B_][kp0 + 3][lrow] = h_; sBl[B_][kp0 + 3][lrow] = l_;                  \
} while (0)

// A hoisted (32 regs); B frags loaded per-fn to cap register pressure.
#define COMPUTE_BF(B_) do {                                                    \
    unsigned Ah_[4][4], Al_[4][4];                                             \
    _Pragma("unroll")                                                          \
    for (int fm_ = 0; fm_ < 4; fm_++) {                                        \
        int mb_ = wm + fm_ * 16;                                               \
        Ah_[fm_][0] = sAh[B_][tig][mb_ + g];                                   \
        Ah_[fm_][1] = sAh[B_][tig][mb_ + g + 8];                               \
        Ah_[fm_][2] = sAh[B_][tig + 4][mb_ + g];                               \
        Ah_[fm_][3] = sAh[B_][tig + 4][mb_ + g + 8];                           \
        Al_[fm_][0] = sAl[B_][tig][mb_ + g];                                   \
        Al_[fm_][1] = sAl[B_][tig][mb_ + g + 8];                               \
        Al_[fm_][2] = sAl[B_][tig + 4][mb_ + g];                               \
        Al_[fm_][3] = sAl[B_][tig + 4][mb_ + g + 8];                           \
    }                                                                          \
    _Pragma("unroll")                                                          \
    for (int fn_ = 0; fn_ < 4; fn_++) {                                        \
        int nb_ = wn + fn_ * 8;                                                \
        unsigned Bh_[2], Bl_[2];                                               \
        Bh_[0] = sBh[B_][tig][nb_ + g];                                        \
        Bh_[1] = sBh[B_][tig + 4][nb_ + g];                                    \
        Bl_[0] = sBl[B_][tig][nb_ + g];                                        \
        Bl_[1] = sBl[B_][tig + 4][nb_ + g];                                    \
        _Pragma("unroll")                                                      \
        for (int fm_ = 0; fm_ < 4; fm_++) {                                    \
            mma_bf16(acc[fm_][fn_], Ah_[fm_], Bh_);                            \
            mma_bf16(acc[fm_][fn_], Ah_[fm_], Bl_);                            \
            mma_bf16(acc[fm_][fn_], Al_[fm_], Bh_);                            \
        }                                                                      \
    }                                                                          \
} while (0)

// ---------------- generic NT GEMM (bf16-split): C = A*B^T + bias -----------
// N%128==0, K%16==0. A must be readable for 128-row tiles (pad A rows);
// stores guarded by m_valid.
__global__ __launch_bounds__(256) void gemm_nt_bf16_kernel(
    const float* __restrict__ A, int lda,
    const float* __restrict__ B, int ldb,
    const float* __restrict__ bias,
    float* __restrict__ C, int ldc, int K, int m_valid)
{
    DECL_TILE_BF();
    const float* Ab = A + (size_t)(blockIdx.x * 128 + lrow) * lda + lk8;
    const float* Bb = B + (size_t)(blockIdx.y * 128 + lrow) * ldb + lk8;
    int NT = K >> 4;
    av0 = *(const float4*)(Ab);     av1 = *(const float4*)(Ab + 4);
    bv0 = *(const float4*)(Bb);     bv1 = *(const float4*)(Bb + 4);
    STORE_SMEM_BF(0);
    __syncthreads();
    int buf = 0;
    for (int t = 1; t < NT; t++) {
        const float* Ak = Ab + t * 16;
        const float* Bk = Bb + t * 16;
        av0 = *(const float4*)(Ak); av1 = *(const float4*)(Ak + 4);
        bv0 = *(const float4*)(Bk); bv1 = *(const float4*)(Bk + 4);
        COMPUTE_BF(buf);
        STORE_SMEM_BF(buf ^ 1);
        __syncthreads();
        buf ^= 1;
    }
    COMPUTE_BF(buf);
    int m0 = blockIdx.x * 128 + wm;
    int n0 = blockIdx.y * 128 + wn;
#pragma unroll
    for (int fm = 0; fm < 4; fm++)
#pragma unroll
        for (int fn = 0; fn < 4; fn++) {
            int r = m0 + fm * 16 + g;
            int c = n0 + fn * 8 + 2 * tig;
            float2 bb = *(const float2*)(bias + c);
            float2 v0, v1;
            v0.x = acc[fm][fn][0] + bb.x; v0.y = acc[fm][fn][1] + bb.y;
            v1.x = acc[fm][fn][2] + bb.x; v1.y = acc[fm][fn][3] + bb.y;
            if (r < m_valid)     *(float2*)(C + (size_t)r * ldc + c) = v0;
            if (r + 8 < m_valid) *(float2*)(C + (size_t)(r + 8) * ldc + c) = v1;
        }
}

// Image-patch A load: k-tile kt -> (channel c = kt>>4, patch-row rr = kt&15),
// 16 contiguous pixels per k-tile.
#define LOAD_IMG(kt_) do {                                                     \
    int c_ = (kt_) >> 4, rr_ = (kt_) & 15;                                     \
    const float* ap_ = Arow + (size_t)(c_ * IMG_H + gh * 16 + rr_) * IMG_W;    \
    av0 = *(const float4*)(ap_); av1 = *(const float4*)(ap_ + 4);              \
    const float* bp_ = Bb + (size_t)(kt_) * 16;                                \
    bv0 = *(const float4*)(bp_); bv1 = *(const float4*)(bp_ + 4);              \
} while (0)

// ---------------- patch-embed GEMM for x (6 views, C_in=3, K=768) ----------
// out: g_tokens[v][s][d] = (sum + bias[d]) * maskf[s]
__global__ __launch_bounds__(256) void gemm_tokens_bf16_kernel(
    const float* __restrict__ x, const float* __restrict__ W,
    const float* __restrict__ bias)
{
    DECL_TILE_BF();
    int v = blockIdx.z;
    const float* img = x + (size_t)v * 3 * IMG_H * IMG_W;
    int s = blockIdx.x * 128 + lrow;
    int sc = s < S_TOK ? s : (S_TOK - 1);
    int gh = sc / 44, gw = sc % 44;
    const float* Arow = img + gw * 16 + lk8;
    const float* Bb = W + (size_t)(blockIdx.y * 128 + lrow) * 768 + lk8;

    LOAD_IMG(0);
    STORE_SMEM_BF(0);
    __syncthreads();
    int buf = 0;
    for (int t = 1; t < 48; t++) {
        LOAD_IMG(t);
        COMPUTE_BF(buf);
        STORE_SMEM_BF(buf ^ 1);
        __syncthreads();
        buf ^= 1;
    }
    COMPUTE_BF(buf);
    int m0 = blockIdx.x * 128 + wm;
    int n0 = blockIdx.y * 128 + wn;
    float* out = g_tokens + (size_t)v * S_TOK * DMODEL;
#pragma unroll
    for (int fm = 0; fm < 4; fm++)
#pragma unroll
        for (int fn = 0; fn < 4; fn++) {
            int r = m0 + fm * 16 + g;
            int c = n0 + fn * 8 + 2 * tig;
            float2 bb = *(const float2*)(bias + c);
            if (r < S_TOK) {
                float mk = g_maskf[r];
                float2 v0;
                v0.x = (acc[fm][fn][0] + bb.x) * mk;
                v0.y = (acc[fm][fn][1] + bb.y) * mk;
                *(float2*)(out + (size_t)r * DMODEL + c) = v0;
            }
            if (r + 8 < S_TOK) {
                float mk = g_maskf[r + 8];
                float2 v1;
                v1.x = (acc[fm][fn][2] + bb.x) * mk;
                v1.y = (acc[fm][fn][3] + bb.y) * mk;
                *(float2*)(out + (size_t)(r + 8) * DMODEL + c) = v1;
            }
        }
}

// ---------------- patch-embed GEMM for pe (K=65536), split-K ---------------
// Each z handles 4096/SPLITK k-tiles -> partials in g_fpart[z] (no bias).
__global__ __launch_bounds__(256) void gemm_pe_bf16_kernel(
    const float* __restrict__ pe, const float* __restrict__ W,
    const int* __restrict__ ftp)
{
    DECL_TILE_BF();
    int z = blockIdx.z;
    const float* img = pe + (size_t)(*ftp) * 256 * IMG_H * IMG_W;
    int s = blockIdx.x * 128 + lrow;
    int sc = s < S_TOK ? s : (S_TOK - 1);
    int gh = sc / 44, gw = sc % 44;
    const float* Arow = img + gw * 16 + lk8;
    const float* Bb = W + (size_t)(blockIdx.y * 128 + lrow) * 65536 + lk8;
    const int KT = 4096 / SPLITK;
    int kt0 = z * KT;

    LOAD_IMG(kt0);
    STORE_SMEM_BF(0);
    __syncthreads();
    int buf = 0;
    for (int t = 1; t < KT; t++) {
        LOAD_IMG(kt0 + t);
        COMPUTE_BF(buf);
        STORE_SMEM_BF(buf ^ 1);
        __syncthreads();
        buf ^= 1;
    }
    COMPUTE_BF(buf);
    int m0 = blockIdx.x * 128 + wm;
    int n0 = blockIdx.y * 128 + wn;
    float* out = g_fpart + (size_t)z * S_TOK * DMODEL;
#pragma unroll
    for (int fm = 0; fm < 4; fm++)
#pragma unroll
        for (int fn = 0; fn < 4; fn++) {
            int r = m0 + fm * 16 + g;
            int c = n0 + fn * 8 + 2 * tig;
            float2 v0, v1;
            v0.x = acc[fm][fn][0]; v0.y = acc[fm][fn][1];
            v1.x = acc[fm][fn][2]; v1.y = acc[fm][fn][3];
            if (r < S_TOK)     *(float2*)(out + (size_t)r * DMODEL + c) = v0;
            if (r + 8 < S_TOK) *(float2*)(out + (size_t)(r + 8) * DMODEL + c) = v1;
        }
}

// Reduce split-K partials (float4-vectorized), add bias, apply mask -> g_fpe
__global__ void fpe_reduce_kernel(const float* __restrict__ peb) {
    int idx = blockIdx.x * blockDim.x + threadIdx.x;   // float4 index
    if (idx >= (S_TOK * DMODEL) / 4) return;
    int s = idx >> 7;                 // 128 float4 per row of 512
    int d4 = idx & 127;
    float4 a = make_float4(0.f, 0.f, 0.f, 0.f);
#pragma unroll
    for (int z = 0; z < SPLITK; z++) {
        float4 p = *(const float4*)(g_fpart + (size_t)z * S_TOK * DMODEL + idx * 4);
        a.x += p.x; a.y += p.y; a.z += p.z; a.w += p.w;
    }
    float4 bb = *(const float4*)(peb + d4 * 4);
    float mk = g_maskf[s];
    float4 r;
    r.x = (a.x + bb.x) * mk; r.y = (a.y + bb.y) * mk;
    r.z = (a.z + bb.z) * mk; r.w = (a.w + bb.w) * mk;
    *(float4*)(g_fpe + idx * 4) = r;
}

// ---------------- q = qkv[ft].q + fpe, then l2-normalize -> g_qn -----------
__global__ void qn_kernel(const int* __restrict__ ftp) {
    int gw = (blockIdx.x * blockDim.x + threadIdx.x) >> 5;
    int lane = threadIdx.x & 31;
    if (gw >= NHEADS * S_TOK) return;
    int h = gw / S_TOK, s = gw % S_TOK;
    int ft = *ftp;
    const float* q = g_qkv + ((size_t)ft * S_TOK + s) * 1536 + h * 192;
    const float* f = g_fpe + (size_t)s * DMODEL + h * 64;
    float v1 = q[lane] + f[lane];
    float v2 = q[lane + 32] + f[lane + 32];
    float ss = v1 * v1 + v2 * v2;
#pragma unroll
    for (int o = 16; o; o >>= 1) ss += __shfl_xor_sync(0xffffffffu, ss, o);
    float inv = 1.f / fmaxf(sqrtf(ss), 1e-12f);
    float* o_ = g_qn + ((size_t)h * S_TOK + s) * HDIM;
    o_[lane] = v1 * inv;
    o_[lane + 32] = v2 * inv;
}

// ---------------- k (normalized) and v (raw) for the 5 other views ---------
__global__ void kvn_kernel(const int* __restrict__ ftp) {
    int gw = (blockIdx.x * blockDim.x + threadIdx.x) >> 5;
    int lane = threadIdx.x & 31;
    if (gw >= NHEADS * TKV) return;
    int h = gw / TKV, t = gw % TKV;
    int vi = t / S_TOK, s = t % S_TOK;
    int ft = *ftp;
    int ov = vi + (vi >= ft ? 1 : 0);
    const float* base = g_qkv + ((size_t)ov * S_TOK + s) * 1536 + h * 192;
    float k1 = base[64 + lane];
    float k2 = base[96 + lane];
    float ss = k1 * k1 + k2 * k2;
#pragma unroll
    for (int o = 16; o; o >>= 1) ss += __shfl_xor_sync(0xffffffffu, ss, o);
    float inv = 1.f / fmaxf(sqrtf(ss), 1e-12f);
    float* ko = g_kn + ((size_t)h * TKV + t) * HDIM;
    ko[lane] = k1 * inv;
    ko[lane + 32] = k2 * inv;
    float* vo = g_vv + ((size_t)h * TKV + t) * HDIM;
    vo[lane] = base[128 + lane];
    vo[lane + 32] = base[160 + lane];
}

// ---------------- landmarks (uniform bin means) ----------------------------
__global__ void qland_kernel() {
    int idx = blockIdx.x * blockDim.x + threadIdx.x;
    if (idx >= NHEADS * LMK * HDIM) return;
    int e = idx & 63, l = (idx >> 6) & 15, h = idx >> 10;
    const float* base = g_qn + ((size_t)h * S_TOK + l * 44) * HDIM + e;
    float a = 0.f;
    for (int i = 0; i < 44; i++) a += base[(size_t)i * HDIM];
    g_qL[idx] = a * (1.f / 44.f);
}
__global__ void kland_kernel() {
    int idx = blockIdx.x * blockDim.x + threadIdx.x;
    if (idx >= NHEADS * LMK * HDIM) return;
    int e = idx & 63, l = (idx >> 6) & 15, h = idx >> 10;
    const float* base = g_kn + ((size_t)h * TKV + l * 220) * HDIM + e;
    float a = 0.f;
    for (int i = 0; i < 220; i++) a += base[(size_t)i * HDIM];
    g_kL[idx] = a * (1.f / 220.f);
}

// ---------------- a1 = softmax_l(qn . kL * scale) --------------------------
__global__ void a1_kernel() {
    int b = blockIdx.x;               // h*704 + s
    int lane = threadIdx.x;
    int h = b / S_TOK, s = b % S_TOK;
    const float* q = g_qn + ((size_t)h * S_TOK + s) * HDIM;
    float q1 = q[lane], q2 = q[lane + 32];
    const float* kl = g_kL + (size_t)h * LMK * HDIM;
    float dot[LMK];
#pragma unroll
    for (int l = 0; l < LMK; l++) {
        float p = q1 * kl[l * HDIM + lane] + q2 * kl[l * HDIM + lane + 32];
#pragma unroll
        for (int o = 16; o; o >>= 1) p += __shfl_xor_sync(0xffffffffu, p, o);
        dot[l] = p * 0.125f;
    }
    float m = dot[0];
#pragma unroll
    for (int l = 1; l < LMK; l++) m = fmaxf(m, dot[l]);
    float sm = 0.f;
#pragma unroll
    for (int l = 0; l < LMK; l++) { dot[l] = expf(dot[l] - m); sm += dot[l]; }
    float inv = 1.f / sm;
    if (lane < LMK)
        g_a1[((size_t)h * S_TOK + s) * LMK + lane] = dot[lane] * inv;
}

// ---------------- a2 = softmax_t(qL . kn * scale); tmp = a2 @ v ------------
__global__ __launch_bounds__(256) void a2_kernel() {
    __shared__ float sq[HDIM];
    __shared__ float red[256];
    __shared__ float p[TKV];
    int hb = blockIdx.x;
    int h = hb >> 4, l = hb & 15;
    int tid = threadIdx.x;
    if (tid < HDIM) sq[tid] = g_qL[((size_t)h * LMK + l) * HDIM + tid];
    __syncthreads();
    const float4* sq4 = (const float4*)sq;
    float lmax = -1e30f;
    for (int t = tid; t < TKV; t += 256) {
        const float4* kr = (const float4*)(g_kn + ((size_t)h * TKV + t) * HDIM);
        float d = 0.f;
#pragma unroll
        for (int i = 0; i < 16; i++) {
            float4 a = sq4[i], b = kr[i];
            d += a.x * b.x + a.y * b.y + a.z * b.z + a.w * b.w;
        }
        d *= 0.125f;
        p[t] = d;
        lmax = fmaxf(lmax, d);
    }
    red[tid] = lmax;
    __syncthreads();
    for (int o = 128; o; o >>= 1) {
        if (tid < o) red[tid] = fmaxf(red[tid], red[tid + o]);
        __syncthreads();
    }
    float M = red[0];
    __syncthreads();
    float lsum = 0.f;
    for (int t = tid; t < TKV; t += 256) {
        float e = expf(p[t] - M);
        p[t] = e;
        lsum += e;
    }
    red[tid] = lsum;
    __syncthreads();
    for (int o = 128; o; o >>= 1) {
        if (tid < o) red[tid] += red[tid + o];
        __syncthreads();
    }
    float inv = 1.f / red[0];
    __syncthreads();
    int e = tid & 63, gq = tid >> 6;
    float acc2 = 0.f;
    for (int t = gq; t < TKV; t += 4)
        acc2 += p[t] * g_vv[((size_t)h * TKV + t) * HDIM + e];
    red[tid] = acc2;
    __syncthreads();
    if (tid < HDIM)
        g_tmp[((size_t)h * LMK + l) * HDIM + tid] =
            (red[tid] + red[tid + 64] + red[tid + 128] + red[tid + 192]) * inv;
}

// ---------------- vals = a1 @ tmp, laid out (s, h*64+e) --------------------
__global__ void vals_kernel() {
    int idx = blockIdx.x * blockDim.x + threadIdx.x;
    if (idx >= S_TOK * DMODEL) return;
    int s = idx >> 9, d = idx & 511;
    int h = d >> 6, e = d & 63;
    const float* a = g_a1 + ((size_t)h * S_TOK + s) * LMK;
    const float* t = g_tmp + (size_t)h * LMK * HDIM + e;
    float acc2 = 0.f;
#pragma unroll
    for (int l = 0; l < LMK; l++) acc2 += a[l] * t[(size_t)l * HDIM];
    g_vals[idx] = acc2;
}

// ---------------- launch ---------------------------------------------------
extern "C" void kernel_launch(void* const* d_in, const int* in_sizes, int n_in,
                              void* d_out, int out_size)
{
    const float* x   = (const float*)d_in[0];
    const float* pe  = (const float*)d_in[1];
    const float* mm  = (const float*)d_in[2];
    const float* ciw = (const float*)d_in[3];
    const float* cib = (const float*)d_in[4];
    const float* cpw = (const float*)d_in[5];
    const float* cpb = (const float*)d_in[6];
    const float* qw  = (const float*)d_in[7];
    const float* qb  = (const float*)d_in[8];
    const float* ow  = (const float*)d_in[9];
    const float* ob  = (const float*)d_in[10];
    const int*   ftp = (const int*)d_in[11];
    float* out = (float*)d_out;

    float *p_tokens, *p_qkv, *p_vals;
    cudaGetSymbolAddress((void**)&p_tokens, g_tokens);
    cudaGetSymbolAddress((void**)&p_qkv, g_qkv);
    cudaGetSymbolAddress((void**)&p_vals, g_vals);

    maskf_kernel<<<3, 256>>>(mm);

    // pe patch-embed (dominant GEMM): (704 x 512) @ W^T, K=65536, split-K
    dim3 gp(6, 4, SPLITK);
    gemm_pe_bf16_kernel<<<gp, 256>>>(pe, cpw, ftp);

    // tokens patch-embed (6 views, K=768)
    dim3 gt(6, 4, 6);
    gemm_tokens_bf16_kernel<<<gt, 256>>>(x, ciw, cib);

    fpe_reduce_kernel<<<(S_TOK * DMODEL / 4 + 255) / 256, 256>>>(cpb);

    // qkv for all 6 views: (4224 x 512) @ (1536 x 512)^T
    gemm_nt_bf16_kernel<<<dim3(33, 12), 256>>>(p_tokens, 512, qw, 512, qb,
                                               p_qkv, 1536, 512, 4224);

    qn_kernel<<<(NHEADS * S_TOK * 32 + 255) / 256, 256>>>(ftp);
    kvn_kernel<<<(NHEADS * TKV * 32 + 255) / 256, 256>>>(ftp);
    qland_kernel<<<(NHEADS * LMK * HDIM + 255) / 256, 256>>>();
    kland_kernel<<<(NHEADS * LMK * HDIM + 255) / 256, 256>>>();
    a1_kernel<<<NHEADS * S_TOK, 32>>>();
    a2_kernel<<<NHEADS * LMK, 256>>>();
    vals_kernel<<<(S_TOK * DMODEL + 255) / 256, 256>>>();

    // out = vals(704x512) @ o_w(512x512)^T + o_b   (g_vals padded to 768 rows)
    gemm_nt_bf16_kernel<<<dim3(6, 4), 256>>>(p_vals, 512, ow, 512, ob,
                                             out, 512, 512, 704);
}